// round 10
// baseline (speedup 1.0000x reference)
#include <cuda_runtime.h>
#include <cuda_bf16.h>

#define IN_F  8192
#define OUT_F 8192
#define THRESH 50.0f
#define NTHREADS 256
#define VPT (IN_F / 4 / NTHREADS)   // 8 float4 per thread

__global__ __launch_bounds__(NTHREADS, 3)   // 80-reg budget (best from R8)
void snn_fused_kernel(const float* __restrict__ x,
                      const float* __restrict__ syn,
                      const float* __restrict__ mem,
                      const float* __restrict__ thr,
                      const float* __restrict__ trace,
                      const float* __restrict__ refr,
                      float* __restrict__ out_spk,
                      float* __restrict__ out_mem,
                      float* __restrict__ out_trace,
                      float* __restrict__ out_refr)
{
    __shared__ float sx[IN_F];              // 32 KB staged spike input
    __shared__ float swarp[NTHREADS / 32];

    const int row = blockIdx.x;
    const int tid = threadIdx.x;

    // ---- stage x into shared (source stays L2-resident: 32 KB total) ----
    {
        const float4* __restrict__ x4  = reinterpret_cast<const float4*>(x);
        float4*                    sx4 = reinterpret_cast<float4*>(sx);
        #pragma unroll
        for (int j = 0; j < VPT; ++j)
            sx4[tid + j * NTHREADS] = x4[tid + j * NTHREADS];
    }
    __syncthreads();

    const float4* __restrict__ syn4 =
        reinterpret_cast<const float4*>(syn + (size_t)row * IN_F);
    const float4* __restrict__ tr4 =
        reinterpret_cast<const float4*>(trace + (size_t)row * IN_F);
    const float4* __restrict__ sx4 = reinterpret_cast<const float4*>(sx);

    // ---- fused pass: pairwise-interleaved syn + trace loads (R5 pattern,
    //      best measured DRAM%); trace prefetched into registers ----
    float4 t[VPT];
    float acc0 = 0.0f, acc1 = 0.0f;
    #pragma unroll
    for (int j = 0; j < VPT; ++j) {
        const int idx = tid + j * NTHREADS;
        const float4 s  = __ldcs(&syn4[idx]);   // streaming, evict-first
        t[j]            = __ldcs(&tr4[idx]);    // no dep on spike until store
        const float4 xv = sx4[idx];
        acc0 += (s.x > THRESH) ? xv.x : 0.0f;
        acc1 += (s.y > THRESH) ? xv.y : 0.0f;
        acc0 += (s.z > THRESH) ? xv.z : 0.0f;
        acc1 += (s.w > THRESH) ? xv.w : 0.0f;
    }
    float acc = acc0 + acc1;

    // warp reduce
    #pragma unroll
    for (int o = 16; o > 0; o >>= 1)
        acc += __shfl_down_sync(0xffffffffu, acc, o);
    if ((tid & 31) == 0) swarp[tid >> 5] = acc;
    __syncthreads();                            // the ONLY post-load barrier

    // all threads redundantly compute the (uniform) LIF scalars
    float current = 0.0f;
    #pragma unroll
    for (int w = 0; w < NTHREADS / 32; ++w) current += swarp[w];
    const float r     = refr[row];
    const float v_mem = mem[row] * 0.5f + current * (1.0f - r * 0.5f);
    const float sp    = (v_mem >= thr[row]) ? 1.0f : 0.0f;
    if (tid == 0) {
        out_spk[row]  = sp;
        out_mem[row]  = v_mem * (1.0f - sp);
        out_refr[row] = fminf(fmaxf(r + sp - 0.1f, 0.0f), 1.0f);
    }

    // ---- store pass: trace already in registers, only the store waited ----
    float4* __restrict__ ot4 =
        reinterpret_cast<float4*>(out_trace + (size_t)row * IN_F);
    #pragma unroll
    for (int j = 0; j < VPT; ++j) {
        const int idx = tid + j * NTHREADS;
        const float4 xv = sx4[idx];
        float4 o;
        o.x = fminf(fmaxf(fmaf(t[j].x, 0.8f, sp * xv.x), 0.0f), 5.0f);
        o.y = fminf(fmaxf(fmaf(t[j].y, 0.8f, sp * xv.y), 0.0f), 5.0f);
        o.z = fminf(fmaxf(fmaf(t[j].z, 0.8f, sp * xv.z), 0.0f), 5.0f);
        o.w = fminf(fmaxf(fmaf(t[j].w, 0.8f, sp * xv.w), 0.0f), 5.0f);
        __stcs(&ot4[idx], o);                   // streaming store, evict-first
    }
}

extern "C" void kernel_launch(void* const* d_in, const int* in_sizes, int n_in,
                              void* d_out, int out_size) {
    const float* x     = (const float*)d_in[0];  // spike_input        [8192]
    const float* syn   = (const float*)d_in[1];  // synapse_states     [8192*8192]
    const float* mem   = (const float*)d_in[2];  // membrane_potential [8192]
    const float* thr   = (const float*)d_in[3];  // adaptive_threshold [8192]
    const float* trace = (const float*)d_in[4];  // eligibility_trace  [8192*8192]
    const float* refr  = (const float*)d_in[5];  // refractory_period  [8192]

    float* out = (float*)d_out;
    // output layout: spikes | new_membrane | new_trace | new_refractory
    float* out_spk   = out;
    float* out_mem   = out + OUT_F;
    float* out_trace = out + 2 * OUT_F;
    float* out_refr  = out + 2 * OUT_F + (size_t)OUT_F * IN_F;

    snn_fused_kernel<<<OUT_F, NTHREADS>>>(x, syn, mem, thr, trace, refr,
                                          out_spk, out_mem, out_trace, out_refr);
}

// round 11
// speedup vs baseline: 1.0174x; 1.0174x over previous
#include <cuda_runtime.h>
#include <cuda_bf16.h>

#define IN_F  8192
#define OUT_F 8192
#define THRESH 50.0f
#define NTHREADS 256
#define VPT (IN_F / 4 / NTHREADS)   // 8 float4 per thread

__global__ __launch_bounds__(NTHREADS, 3)   // 80-reg budget
void snn_fused_kernel(const float* __restrict__ x,
                      const float* __restrict__ syn,
                      const float* __restrict__ mem,
                      const float* __restrict__ thr,
                      const float* __restrict__ trace,
                      const float* __restrict__ refr,
                      float* __restrict__ out_spk,
                      float* __restrict__ out_mem,
                      float* __restrict__ out_trace,
                      float* __restrict__ out_refr)
{
    __shared__ float swarp[NTHREADS / 32];   // only cross-thread state left

    const int row = blockIdx.x;
    const int tid = threadIdx.x;

    const float4* __restrict__ x4 = reinterpret_cast<const float4*>(x);
    const float4* __restrict__ syn4 =
        reinterpret_cast<const float4*>(syn + (size_t)row * IN_F);
    const float4* __restrict__ tr4 =
        reinterpret_cast<const float4*>(trace + (size_t)row * IN_F);

    // ---- CRITICAL PATH FIRST: all 8 syn loads (they gate the barrier).
    //      No prologue, no staging barrier — streaming starts at instruction 0.
    float4 s[VPT];
    #pragma unroll
    for (int j = 0; j < VPT; ++j)
        s[j] = __ldcs(&syn4[tid + j * NTHREADS]);

    // x: 32 KB, L1-resident across CTAs within the launch -> __ldca hits L1.
    // Each thread reads exactly its own 8 float4 (per-thread pass-through;
    // this is why the old smem staging was pure overhead).
    float acc0 = 0.0f, acc1 = 0.0f;
    #pragma unroll
    for (int j = 0; j < VPT; ++j) {
        const float4 xv = __ldca(&x4[tid + j * NTHREADS]);
        acc0 += (s[j].x > THRESH) ? xv.x : 0.0f;
        acc1 += (s[j].y > THRESH) ? xv.y : 0.0f;
        acc0 += (s[j].z > THRESH) ? xv.z : 0.0f;
        acc1 += (s[j].w > THRESH) ? xv.w : 0.0f;
    }
    float acc = acc0 + acc1;

    // warp reduce
    #pragma unroll
    for (int o = 16; o > 0; o >>= 1)
        acc += __shfl_down_sync(0xffffffffu, acc, o);
    if ((tid & 31) == 0) swarp[tid >> 5] = acc;

    // ---- SLACK PATH: trace loads issued into the barrier-wait shadow ----
    float4 t[VPT];
    #pragma unroll
    for (int j = 0; j < VPT; ++j)
        t[j] = __ldcs(&tr4[tid + j * NTHREADS]);

    __syncthreads();                            // the ONLY barrier

    // all threads redundantly compute the (uniform) LIF scalars
    float current = 0.0f;
    #pragma unroll
    for (int w = 0; w < NTHREADS / 32; ++w) current += swarp[w];
    const float r     = refr[row];
    const float v_mem = mem[row] * 0.5f + current * (1.0f - r * 0.5f);
    const float sp    = (v_mem >= thr[row]) ? 1.0f : 0.0f;
    if (tid == 0) {
        out_spk[row]  = sp;
        out_mem[row]  = v_mem * (1.0f - sp);
        out_refr[row] = fminf(fmaxf(r + sp - 0.1f, 0.0f), 1.0f);
    }

    // ---- store pass: trace already in registers, only the store waited ----
    float4* __restrict__ ot4 =
        reinterpret_cast<float4*>(out_trace + (size_t)row * IN_F);
    #pragma unroll
    for (int j = 0; j < VPT; ++j) {
        const int idx = tid + j * NTHREADS;
        const float4 xv = __ldca(&x4[idx]);     // L1 hit
        float4 o;
        o.x = fminf(fmaxf(fmaf(t[j].x, 0.8f, sp * xv.x), 0.0f), 5.0f);
        o.y = fminf(fmaxf(fmaf(t[j].y, 0.8f, sp * xv.y), 0.0f), 5.0f);
        o.z = fminf(fmaxf(fmaf(t[j].z, 0.8f, sp * xv.z), 0.0f), 5.0f);
        o.w = fminf(fmaxf(fmaf(t[j].w, 0.8f, sp * xv.w), 0.0f), 5.0f);
        __stcs(&ot4[idx], o);                   // streaming store, evict-first
    }
}

extern "C" void kernel_launch(void* const* d_in, const int* in_sizes, int n_in,
                              void* d_out, int out_size) {
    const float* x     = (const float*)d_in[0];  // spike_input        [8192]
    const float* syn   = (const float*)d_in[1];  // synapse_states     [8192*8192]
    const float* mem   = (const float*)d_in[2];  // membrane_potential [8192]
    const float* thr   = (const float*)d_in[3];  // adaptive_threshold [8192]
    const float* trace = (const float*)d_in[4];  // eligibility_trace  [8192*8192]
    const float* refr  = (const float*)d_in[5];  // refractory_period  [8192]

    float* out = (float*)d_out;
    // output layout: spikes | new_membrane | new_trace | new_refractory
    float* out_spk   = out;
    float* out_mem   = out + OUT_F;
    float* out_trace = out + 2 * OUT_F;
    float* out_refr  = out + 2 * OUT_F + (size_t)OUT_F * IN_F;

    snn_fused_kernel<<<OUT_F, NTHREADS>>>(x, syn, mem, thr, trace, refr,
                                          out_spk, out_mem, out_trace, out_refr);
}

// round 13
// speedup vs baseline: 1.0236x; 1.0060x over previous
#include <cuda_runtime.h>
#include <cuda_bf16.h>

#define IN_F  8192
#define OUT_F 8192
#define THRESH 50.0f
#define NTHREADS 256
#define VPT (IN_F / 4 / NTHREADS)   // 8 float4 per thread

__global__ __launch_bounds__(NTHREADS, 3)   // 80-reg budget
void snn_fused_kernel(const float* __restrict__ x,
                      const float* __restrict__ syn,
                      const float* __restrict__ mem,
                      const float* __restrict__ thr,
                      const float* __restrict__ trace,
                      const float* __restrict__ refr,
                      float* __restrict__ out_spk,
                      float* __restrict__ out_mem,
                      float* __restrict__ out_trace,
                      float* __restrict__ out_refr)
{
    __shared__ float swarp[NTHREADS / 32];

    const int row = blockIdx.x;
    const int tid = threadIdx.x;

    const float4* __restrict__ x4 = reinterpret_cast<const float4*>(x);
    const float4* __restrict__ syn4 =
        reinterpret_cast<const float4*>(syn + (size_t)row * IN_F);
    const float4* __restrict__ tr4 =
        reinterpret_cast<const float4*>(trace + (size_t)row * IN_F);

    // ---- CRITICAL PATH FIRST: all 8 syn loads (they gate the barrier) ----
    float4 s[VPT];
    #pragma unroll
    for (int j = 0; j < VPT; ++j)
        s[j] = __ldcs(&syn4[tid + j * NTHREADS]);

    // Consume syn with x (L1-resident). x is exactly {0.0, 1.0}: compress this
    // thread's 32 x values into one bitmask so the store pass needs NO x loads.
    unsigned int xbits = 0u;
    float acc0 = 0.0f, acc1 = 0.0f;
    #pragma unroll
    for (int j = 0; j < VPT; ++j) {
        const float4 xv = __ldca(&x4[tid + j * NTHREADS]);
        xbits |= (xv.x != 0.0f ? 1u : 0u) << (4 * j + 0);
        xbits |= (xv.y != 0.0f ? 1u : 0u) << (4 * j + 1);
        xbits |= (xv.z != 0.0f ? 1u : 0u) << (4 * j + 2);
        xbits |= (xv.w != 0.0f ? 1u : 0u) << (4 * j + 3);
        acc0 += (s[j].x > THRESH) ? xv.x : 0.0f;
        acc1 += (s[j].y > THRESH) ? xv.y : 0.0f;
        acc0 += (s[j].z > THRESH) ? xv.z : 0.0f;
        acc1 += (s[j].w > THRESH) ? xv.w : 0.0f;
    }
    float acc = acc0 + acc1;

    // warp reduce
    #pragma unroll
    for (int o = 16; o > 0; o >>= 1)
        acc += __shfl_down_sync(0xffffffffu, acc, o);
    if ((tid & 31) == 0) swarp[tid >> 5] = acc;

    // ---- SLACK PATH: trace loads issued into the barrier-wait shadow ----
    float4 t[VPT];
    #pragma unroll
    for (int j = 0; j < VPT; ++j)
        t[j] = __ldcs(&tr4[tid + j * NTHREADS]);

    __syncthreads();                            // the ONLY barrier

    // all threads redundantly compute the (uniform) LIF scalars
    float current = 0.0f;
    #pragma unroll
    for (int w = 0; w < NTHREADS / 32; ++w) current += swarp[w];
    const float r     = refr[row];
    const float v_mem = mem[row] * 0.5f + current * (1.0f - r * 0.5f);
    const float sp    = (v_mem >= thr[row]) ? 1.0f : 0.0f;
    if (tid == 0) {
        out_spk[row]  = sp;
        out_mem[row]  = v_mem * (1.0f - sp);
        out_refr[row] = fminf(fmaxf(r + sp - 0.1f, 0.0f), 1.0f);
    }

    // Fold spike into the mask: sp*x[i] == 1.0 iff sp==1 and x-bit set.
    const unsigned int m = (sp != 0.0f) ? xbits : 0u;

    // ---- store pass: ZERO memory dependencies — stores fire at barrier release ----
    float4* __restrict__ ot4 =
        reinterpret_cast<float4*>(out_trace + (size_t)row * IN_F);
    #pragma unroll
    for (int j = 0; j < VPT; ++j) {
        const float ax = ((m >> (4 * j + 0)) & 1u) ? 1.0f : 0.0f;
        const float ay = ((m >> (4 * j + 1)) & 1u) ? 1.0f : 0.0f;
        const float az = ((m >> (4 * j + 2)) & 1u) ? 1.0f : 0.0f;
        const float aw = ((m >> (4 * j + 3)) & 1u) ? 1.0f : 0.0f;
        float4 o;
        o.x = fminf(fmaxf(fmaf(t[j].x, 0.8f, ax), 0.0f), 5.0f);
        o.y = fminf(fmaxf(fmaf(t[j].y, 0.8f, ay), 0.0f), 5.0f);
        o.z = fminf(fmaxf(fmaf(t[j].z, 0.8f, az), 0.0f), 5.0f);
        o.w = fminf(fmaxf(fmaf(t[j].w, 0.8f, aw), 0.0f), 5.0f);
        __stcs(&ot4[tid + j * NTHREADS], o);    // streaming store, evict-first
    }
}

extern "C" void kernel_launch(void* const* d_in, const int* in_sizes, int n_in,
                              void* d_out, int out_size) {
    const float* x     = (const float*)d_in[0];  // spike_input        [8192]
    const float* syn   = (const float*)d_in[1];  // synapse_states     [8192*8192]
    const float* mem   = (const float*)d_in[2];  // membrane_potential [8192]
    const float* thr   = (const float*)d_in[3];  // adaptive_threshold [8192]
    const float* trace = (const float*)d_in[4];  // eligibility_trace  [8192*8192]
    const float* refr  = (const float*)d_in[5];  // refractory_period  [8192]

    float* out = (float*)d_out;
    // output layout: spikes | new_membrane | new_trace | new_refractory
    float* out_spk   = out;
    float* out_mem   = out + OUT_F;
    float* out_trace = out + 2 * OUT_F;
    float* out_refr  = out + 2 * OUT_F + (size_t)OUT_F * IN_F;

    snn_fused_kernel<<<OUT_F, NTHREADS>>>(x, syn, mem, thr, trace, refr,
                                          out_spk, out_mem, out_trace, out_refr);
}